// round 1
// baseline (speedup 1.0000x reference)
#include <cuda_runtime.h>
#include <math.h>

#define BB 8
#define SS 1024
#define DD 256
#define HH 32
#define INF 64
#define LL 4

// scratch: z (real/imag) in [B][D][S] layout
__device__ float g_zr[BB*DD*SS];
__device__ float g_zi[BB*DD*SS];

__device__ __forceinline__ float gelu_exact(float v){
    return 0.5f * v * (1.0f + erff(v * 0.70710678118654752f));
}

// ---------------------------------------------------------------------------
// Kernel A: embed (x @ er_w + er_b, x @ ei_w + ei_b) + complex rotation,
// write transposed to g_zr/g_zi [B][D][S].
// ---------------------------------------------------------------------------
#define TS 16
__global__ void __launch_bounds__(256) embed_kernel(
    const float* __restrict__ x,
    const float* __restrict__ erw, const float* __restrict__ erb,
    const float* __restrict__ eiw, const float* __restrict__ eib)
{
    __shared__ float xsh[TS][INF];
    __shared__ float zshr[DD][TS+1];
    __shared__ float zshi[DD][TS+1];

    int t = threadIdx.x;                  // 256 threads, thread t owns d = t
    int nb_per_b = SS / TS;               // 64
    int b  = blockIdx.x / nb_per_b;
    int s0 = (blockIdx.x % nb_per_b) * TS;

    // load x tile [TS][64] coalesced
    const float* xp = x + (size_t)(b*SS + s0) * INF;
    for (int i = t; i < TS*INF; i += 256) xsh[i / INF][i % INF] = xp[i];
    __syncthreads();

    int d = t;
    float ar[TS], ai[TS];
    float br = erb[d], bi = eib[d];
    #pragma unroll
    for (int s = 0; s < TS; s++){ ar[s] = br; ai[s] = bi; }

    #pragma unroll 8
    for (int i = 0; i < INF; i++){
        float wr = erw[i*DD + d];
        float wi = eiw[i*DD + d];
        #pragma unroll
        for (int s = 0; s < TS; s++){
            float xv = xsh[s][i];          // broadcast
            ar[s] = fmaf(xv, wr, ar[s]);
            ai[s] = fmaf(xv, wi, ai[s]);
        }
    }

    float freq = (float)exp(-9.210340371976184 * (double)d / 256.0);
    #pragma unroll
    for (int s = 0; s < TS; s++){
        float theta = (float)(s0 + s) * freq;
        float sn, cs;
        sincosf(theta, &sn, &cs);
        zshr[d][s] = ar[s]*cs - ai[s]*sn;
        zshi[d][s] = ar[s]*sn + ai[s]*cs;
    }
    __syncthreads();

    // transposed writeout: consecutive threads write consecutive s
    float* outr = g_zr + (size_t)b * DD * SS;
    float* outi = g_zi + (size_t)b * DD * SS;
    for (int idx = t; idx < DD*TS; idx += 256){
        int dd = idx >> 4;
        int sx = idx & (TS-1);
        outr[dd*SS + s0 + sx] = zshr[dd][sx];
        outi[dd*SS + s0 + sx] = zshi[dd][sx];
    }
}

// ---------------------------------------------------------------------------
// Kernel B: 4 causal polarizing blocks. One block per (b,d) sequence.
// 256 threads x 4 elements. z stays in registers across layers.
// ---------------------------------------------------------------------------
#define NT 256
__global__ void __launch_bounds__(NT) layers_kernel(
    const float* __restrict__ pm_w1, const float* __restrict__ pm_b1,
    const float* __restrict__ pm_w2, const float* __restrict__ pm_b2,
    const float* __restrict__ pp_w1, const float* __restrict__ pp_b1,
    const float* __restrict__ pp_w2, const float* __restrict__ pp_b2,
    const float* __restrict__ mag_scale)
{
    __shared__ float smw1[LL*HH], smb1[LL*HH], smw2[LL*HH];
    __shared__ float spa[LL*HH], spb[LL*HH], spc[LL*HH], spwr[LL*HH], spwi[LL*HH];
    __shared__ float smb2[LL], spb2r[LL], spb2i[LL], sscale[LL];
    __shared__ float warp_r[8], warp_i[8];

    int t = threadIdx.x;
    if (t < LL*HH){
        int l = t / HH, j = t % HH;
        smw1[t] = pm_w1[t];                       // [L,1,H]
        smb1[t] = pm_b1[t];                       // [L,H]
        smw2[t] = pm_w2[t];                       // [L,H,1]
        spa[t]  = pp_w1[l*2*HH + j];              // [L,2,H] c=0
        spb[t]  = pp_w1[l*2*HH + HH + j];         // c=1
        spc[t]  = pp_b1[t];                       // [L,H]
        spwr[t] = pp_w2[t*2];                     // [L,H,2] c=0
        spwi[t] = pp_w2[t*2 + 1];                 // c=1
    }
    if (t < LL){
        smb2[t]  = pm_b2[t];                      // [L,1]
        spb2r[t] = pp_b2[t*2];                    // [L,2]
        spb2i[t] = pp_b2[t*2 + 1];
        sscale[t]= mag_scale[t];
    }

    size_t base = (size_t)blockIdx.x * SS;        // blockIdx = b*D + d
    float4 z4r = ((const float4*)(g_zr + base))[t];
    float4 z4i = ((const float4*)(g_zi + base))[t];
    float zr[4] = {z4r.x, z4r.y, z4r.z, z4r.w};
    float zi[4] = {z4i.x, z4i.y, z4i.z, z4i.w};

    float invc[4];
    #pragma unroll
    for (int k = 0; k < 4; k++) invc[k] = 1.0f / (float)(t*4 + k + 1);

    int lane = t & 31, wid = t >> 5;
    __syncthreads();

    for (int l = 0; l < LL; l++){
        // ---- block-wide inclusive scan of zr, zi (1024 elements) ----
        float c0r = zr[0], c1r = c0r + zr[1], c2r = c1r + zr[2], c3r = c2r + zr[3];
        float c0i = zi[0], c1i = c0i + zi[1], c2i = c1i + zi[2], c3i = c2i + zi[3];
        float wr_ = c3r, wi_ = c3i;
        #pragma unroll
        for (int o = 1; o < 32; o <<= 1){
            float ur = __shfl_up_sync(0xffffffffu, wr_, o);
            float ui = __shfl_up_sync(0xffffffffu, wi_, o);
            if (lane >= o){ wr_ += ur; wi_ += ui; }
        }
        if (lane == 31){ warp_r[wid] = wr_; warp_i[wid] = wi_; }
        __syncthreads();
        float offr = 0.f, offi = 0.f;
        #pragma unroll
        for (int w = 0; w < 7; w++){
            if (w < wid){ offr += warp_r[w]; offi += warp_i[w]; }
        }
        __syncthreads();   // warp_r reused next layer

        float baser = offr + wr_ - c3r;
        float basei = offi + wi_ - c3i;
        float cumr[4] = {baser + c0r, baser + c1r, baser + c2r, baser + c3r};
        float cumi[4] = {basei + c0i, basei + c1i, basei + c2i, basei + c3i};

        // ---- pointwise polarizing math ----
        float lm[4], pr[4], pi[4], delta[4], orr[4], oii[4];
        float b2 = smb2[l], pbr = spb2r[l], pbi = spb2i[l], scale = sscale[l];
        #pragma unroll
        for (int k = 0; k < 4; k++){
            float Ar = cumr[k]*invc[k], Ai = cumi[k]*invc[k];
            float mag = sqrtf(fmaf(Ar, Ar, Ai*Ai));
            float m1  = mag + 1e-6f;
            lm[k] = __logf(m1);
            float inv = __fdividef(1.0f, m1);
            pr[k] = Ar * inv;
            pi[k] = Ai * inv;
            delta[k] = b2; orr[k] = pbr; oii[k] = pbi;
        }

        const float* w1p  = smw1 + l*HH;
        const float* b1p  = smb1 + l*HH;
        const float* w2p  = smw2 + l*HH;
        const float* pap  = spa  + l*HH;
        const float* pbp  = spb  + l*HH;
        const float* pcp  = spc  + l*HH;
        const float* pwrp = spwr + l*HH;
        const float* pwip = spwi + l*HH;

        #pragma unroll 4
        for (int j = 0; j < HH; j++){
            float w1 = w1p[j], b1 = b1p[j], w2 = w2p[j];
            float pa = pap[j], pb = pbp[j], pc = pcp[j];
            float pwr = pwrp[j], pwi = pwip[j];
            #pragma unroll
            for (int k = 0; k < 4; k++){
                float h  = fmaf(lm[k], w1, b1);
                float g  = gelu_exact(h);
                delta[k] = fmaf(g, w2, delta[k]);
                float hp = fmaf(pr[k], pa, fmaf(pi[k], pb, pc));
                float gp = gelu_exact(hp);
                orr[k] = fmaf(gp, pwr, orr[k]);
                oii[k] = fmaf(gp, pwi, oii[k]);
            }
        }

        #pragma unroll
        for (int k = 0; k < 4; k++){
            float lmo  = fmaf(scale, delta[k], lm[k]);
            float nrm  = sqrtf(fmaf(orr[k], orr[k], oii[k]*oii[k]));
            float invn = __fdividef(1.0f, fmaxf(nrm, 1e-12f));
            float r    = __expf(lmo) * invn;
            zr[k] = fmaf(r, orr[k], zr[k]);
            zi[k] = fmaf(r, oii[k], zi[k]);
        }
    }

    // decode needs only the real part
    ((float4*)(g_zr + base))[t] = make_float4(zr[0], zr[1], zr[2], zr[3]);
}

// ---------------------------------------------------------------------------
// Kernel C: decode  preds = gelu(feats @ op_w1 + op_b1) @ op_w2 + op_b2
// warp per (b,s), lane = hidden unit h
// ---------------------------------------------------------------------------
__global__ void __launch_bounds__(256) decode_kernel(
    const float* __restrict__ w1, const float* __restrict__ b1,
    const float* __restrict__ w2, const float* __restrict__ b2,
    float* __restrict__ out)
{
    __shared__ float w1sh[DD*HH];   // 32 KB
    int t = threadIdx.x;
    for (int i = t; i < DD*HH; i += 256) w1sh[i] = w1[i];
    __syncthreads();

    int wid = t >> 5, lane = t & 31;
    int wg = blockIdx.x * 8 + wid;               // [0, B*S)
    int b = wg >> 10, s = wg & (SS - 1);

    const float* fp = g_zr + ((size_t)b * DD) * SS + s;
    float acc = b1[lane];
    #pragma unroll 8
    for (int d = 0; d < DD; d++){
        acc = fmaf(fp[(size_t)d * SS], w1sh[d*HH + lane], acc);
    }
    float g = gelu_exact(acc) * w2[lane];
    #pragma unroll
    for (int o = 16; o; o >>= 1) g += __shfl_down_sync(0xffffffffu, g, o);
    if (lane == 0) out[wg] = g + b2[0];
}

// ---------------------------------------------------------------------------
extern "C" void kernel_launch(void* const* d_in, const int* in_sizes, int n_in,
                              void* d_out, int out_size)
{
    const float* x     = (const float*)d_in[0];
    const float* er_w  = (const float*)d_in[1];
    const float* er_b  = (const float*)d_in[2];
    const float* ei_w  = (const float*)d_in[3];
    const float* ei_b  = (const float*)d_in[4];
    const float* pm_w1 = (const float*)d_in[5];
    const float* pm_b1 = (const float*)d_in[6];
    const float* pm_w2 = (const float*)d_in[7];
    const float* pm_b2 = (const float*)d_in[8];
    const float* pp_w1 = (const float*)d_in[9];
    const float* pp_b1 = (const float*)d_in[10];
    const float* pp_w2 = (const float*)d_in[11];
    const float* pp_b2 = (const float*)d_in[12];
    const float* mscal = (const float*)d_in[13];
    const float* op_w1 = (const float*)d_in[14];
    const float* op_b1 = (const float*)d_in[15];
    const float* op_w2 = (const float*)d_in[16];
    const float* op_b2 = (const float*)d_in[17];
    float* out = (float*)d_out;

    embed_kernel<<<BB*(SS/TS), 256>>>(x, er_w, er_b, ei_w, ei_b);
    layers_kernel<<<BB*DD, NT>>>(pm_w1, pm_b1, pm_w2, pm_b2,
                                 pp_w1, pp_b1, pp_w2, pp_b2, mscal);
    decode_kernel<<<BB*SS/8, 256>>>(op_w1, op_b1, op_w2, op_b2, out);
}

// round 2
// speedup vs baseline: 2.5275x; 2.5275x over previous
#include <cuda_runtime.h>
#include <math.h>

#define BB 8
#define SS 1024
#define DD 256
#define HH 32
#define INF 64
#define LL 4

typedef unsigned long long u64;

// scratch: z (real/imag) in [B][D][S] layout
__device__ float g_zr[BB*DD*SS];
__device__ float g_zi[BB*DD*SS];

__device__ __forceinline__ float gelu_exact(float v){
    return 0.5f * v * (1.0f + erff(v * 0.70710678118654752f));
}

// ---- f32x2 packed helpers (sm_100+) ----
__device__ __forceinline__ u64 pk2(float lo, float hi){
    u64 r; asm("mov.b64 %0, {%1, %2};" : "=l"(r) : "f"(lo), "f"(hi)); return r;
}
__device__ __forceinline__ void upk2(u64 v, float &lo, float &hi){
    asm("mov.b64 {%0, %1}, %2;" : "=f"(lo), "=f"(hi) : "l"(v));
}
__device__ __forceinline__ u64 fma2(u64 a, u64 b, u64 c){
    u64 r; asm("fma.rn.f32x2 %0, %1, %2, %3;" : "=l"(r) : "l"(a), "l"(b), "l"(c)); return r;
}
__device__ __forceinline__ u64 mul2(u64 a, u64 b){
    u64 r; asm("mul.rn.f32x2 %0, %1, %2;" : "=l"(r) : "l"(a), "l"(b)); return r;
}
__device__ __forceinline__ float tanh_ap(float x){
    float y; asm("tanh.approx.f32 %0, %1;" : "=f"(y) : "f"(x)); return y;
}
__device__ __forceinline__ u64 tanh2(u64 v){
    float lo, hi; upk2(v, lo, hi);
    return pk2(tanh_ap(lo), tanh_ap(hi));
}
__device__ __forceinline__ float sqrt_ap(float x){
    float y; asm("sqrt.approx.f32 %0, %1;" : "=f"(y) : "f"(x)); return y;
}
__device__ __forceinline__ float rcp_ap(float x){
    float y; asm("rcp.approx.f32 %0, %1;" : "=f"(y) : "f"(x)); return y;
}

// ---------------------------------------------------------------------------
// Kernel A: embed (x @ er_w + er_b, x @ ei_w + ei_b) + complex rotation,
// write transposed to g_zr/g_zi [B][D][S].
// ---------------------------------------------------------------------------
#define TS 16
__global__ void __launch_bounds__(256) embed_kernel(
    const float* __restrict__ x,
    const float* __restrict__ erw, const float* __restrict__ erb,
    const float* __restrict__ eiw, const float* __restrict__ eib)
{
    __shared__ float xsh[TS][INF];
    __shared__ float zshr[DD][TS+1];
    __shared__ float zshi[DD][TS+1];

    int t = threadIdx.x;                  // 256 threads, thread t owns d = t
    int nb_per_b = SS / TS;               // 64
    int b  = blockIdx.x / nb_per_b;
    int s0 = (blockIdx.x % nb_per_b) * TS;

    const float* xp = x + (size_t)(b*SS + s0) * INF;
    for (int i = t; i < TS*INF; i += 256) xsh[i / INF][i % INF] = xp[i];
    __syncthreads();

    int d = t;
    float ar[TS], ai[TS];
    float br = erb[d], bi = eib[d];
    #pragma unroll
    for (int s = 0; s < TS; s++){ ar[s] = br; ai[s] = bi; }

    #pragma unroll 8
    for (int i = 0; i < INF; i++){
        float wr = erw[i*DD + d];
        float wi = eiw[i*DD + d];
        #pragma unroll
        for (int s = 0; s < TS; s++){
            float xv = xsh[s][i];
            ar[s] = fmaf(xv, wr, ar[s]);
            ai[s] = fmaf(xv, wi, ai[s]);
        }
    }

    float freq = (float)exp(-9.210340371976184 * (double)d / 256.0);
    #pragma unroll
    for (int s = 0; s < TS; s++){
        float theta = (float)(s0 + s) * freq;
        float sn, cs;
        sincosf(theta, &sn, &cs);
        zshr[d][s] = ar[s]*cs - ai[s]*sn;
        zshi[d][s] = ar[s]*sn + ai[s]*cs;
    }
    __syncthreads();

    float* outr = g_zr + (size_t)b * DD * SS;
    float* outi = g_zi + (size_t)b * DD * SS;
    for (int idx = t; idx < DD*TS; idx += 256){
        int dd = idx >> 4;
        int sx = idx & (TS-1);
        outr[dd*SS + s0 + sx] = zshr[dd][sx];
        outi[dd*SS + s0 + sx] = zshi[dd][sx];
    }
}

// ---------------------------------------------------------------------------
// Kernel B: 4 causal polarizing blocks. One block per (b,d) sequence.
// 256 threads x 4 elements (2 packed f32x2 pairs). z in registers across layers.
// GELU = tanh.approx formulation; 0.5 folded into second-layer weights.
// ---------------------------------------------------------------------------
#define NT 256
__global__ void __launch_bounds__(NT) layers_kernel(
    const float* __restrict__ pm_w1, const float* __restrict__ pm_b1,
    const float* __restrict__ pm_w2, const float* __restrict__ pm_b2,
    const float* __restrict__ pp_w1, const float* __restrict__ pp_b1,
    const float* __restrict__ pp_w2, const float* __restrict__ pp_b2,
    const float* __restrict__ mag_scale)
{
    // packed (splatted) weights: [l][j][8] = w1,b1,w2h,pc,pa,pb,pwrh,pwih
    __shared__ u64 Wsh[LL][HH][8];
    __shared__ float smb2[LL], spb2r[LL], spb2i[LL], sscale[LL];
    __shared__ float warp_r[8], warp_i[8];

    int t = threadIdx.x;
    if (t < LL*HH){
        int l = t / HH, j = t % HH;
        float w1  = pm_w1[t];                    // [L,1,H]
        float b1  = pm_b1[t];                    // [L,H]
        float w2h = 0.5f * pm_w2[t];             // [L,H,1]
        float pa  = pp_w1[l*2*HH + j];           // [L,2,H] c=0
        float pb  = pp_w1[l*2*HH + HH + j];      // c=1
        float pc  = pp_b1[t];                    // [L,H]
        float pwrh= 0.5f * pp_w2[t*2];           // [L,H,2] c=0
        float pwih= 0.5f * pp_w2[t*2 + 1];       // c=1
        Wsh[l][j][0] = pk2(w1, w1);
        Wsh[l][j][1] = pk2(b1, b1);
        Wsh[l][j][2] = pk2(w2h, w2h);
        Wsh[l][j][3] = pk2(pc, pc);
        Wsh[l][j][4] = pk2(pa, pa);
        Wsh[l][j][5] = pk2(pb, pb);
        Wsh[l][j][6] = pk2(pwrh, pwrh);
        Wsh[l][j][7] = pk2(pwih, pwih);
    }
    if (t < LL){
        smb2[t]  = pm_b2[t];
        spb2r[t] = pp_b2[t*2];
        spb2i[t] = pp_b2[t*2 + 1];
        sscale[t]= mag_scale[t];
    }

    size_t base = (size_t)blockIdx.x * SS;        // blockIdx = b*D + d
    float4 z4r = ((const float4*)(g_zr + base))[t];
    float4 z4i = ((const float4*)(g_zi + base))[t];
    float zr[4] = {z4r.x, z4r.y, z4r.z, z4r.w};
    float zi[4] = {z4i.x, z4i.y, z4i.z, z4i.w};

    float invc[4];
    #pragma unroll
    for (int k = 0; k < 4; k++) invc[k] = 1.0f / (float)(t*4 + k + 1);

    int lane = t & 31, wid = t >> 5;
    const u64 A2 = pk2(0.7978845608028654f, 0.7978845608028654f);
    const u64 B2 = pk2(0.035677408136300125f, 0.035677408136300125f);
    __syncthreads();

    for (int l = 0; l < LL; l++){
        // ---- block-wide inclusive scan of zr, zi ----
        float c0r = zr[0], c1r = c0r + zr[1], c2r = c1r + zr[2], c3r = c2r + zr[3];
        float c0i = zi[0], c1i = c0i + zi[1], c2i = c1i + zi[2], c3i = c2i + zi[3];
        float wr_ = c3r, wi_ = c3i;
        #pragma unroll
        for (int o = 1; o < 32; o <<= 1){
            float ur = __shfl_up_sync(0xffffffffu, wr_, o);
            float ui = __shfl_up_sync(0xffffffffu, wi_, o);
            if (lane >= o){ wr_ += ur; wi_ += ui; }
        }
        if (lane == 31){ warp_r[wid] = wr_; warp_i[wid] = wi_; }
        __syncthreads();
        float offr = 0.f, offi = 0.f;
        #pragma unroll
        for (int w = 0; w < 7; w++){
            if (w < wid){ offr += warp_r[w]; offi += warp_i[w]; }
        }
        __syncthreads();

        float baser = offr + wr_ - c3r;
        float basei = offi + wi_ - c3i;
        float cumr[4] = {baser + c0r, baser + c1r, baser + c2r, baser + c3r};
        float cumi[4] = {basei + c0i, basei + c1i, basei + c2i, basei + c3i};

        // ---- per-element prologue: mean, magnitude, log-mag, unit phase ----
        float lm[4], pr[4], pi[4];
        #pragma unroll
        for (int k = 0; k < 4; k++){
            float Ar = cumr[k]*invc[k], Ai = cumi[k]*invc[k];
            float mag = sqrt_ap(fmaf(Ar, Ar, Ai*Ai));
            float m1  = mag + 1e-6f;
            lm[k] = __logf(m1);
            float inv = rcp_ap(m1);
            pr[k] = Ar * inv;
            pi[k] = Ai * inv;
        }

        float b2 = smb2[l], pbr = spb2r[l], pbi = spb2i[l], scale = sscale[l];
        u64 lm2[2] = { pk2(lm[0], lm[1]), pk2(lm[2], lm[3]) };
        u64 pr2[2] = { pk2(pr[0], pr[1]), pk2(pr[2], pr[3]) };
        u64 pi2[2] = { pk2(pi[0], pi[1]), pk2(pi[2], pi[3]) };
        u64 d2[2]  = { pk2(b2, b2),  pk2(b2, b2)  };
        u64 or2[2] = { pk2(pbr, pbr), pk2(pbr, pbr) };
        u64 oi2[2] = { pk2(pbi, pbi), pk2(pbi, pbi) };

        const u64* wp = &Wsh[l][0][0];
        #pragma unroll 2
        for (int j = 0; j < HH; j++){
            ulonglong2 c01 = *(const ulonglong2*)(wp + j*8 + 0); // w1, b1
            ulonglong2 c23 = *(const ulonglong2*)(wp + j*8 + 2); // w2h, pc
            ulonglong2 c45 = *(const ulonglong2*)(wp + j*8 + 4); // pa, pb
            ulonglong2 c67 = *(const ulonglong2*)(wp + j*8 + 6); // pwrh, pwih
            #pragma unroll
            for (int p = 0; p < 2; p++){
                // psi_mag: h -> gelu -> acc   (gelu = 0.5 h (1+tanh(h(A+B h^2))))
                u64 h   = fma2(lm2[p], c01.x, c01.y);
                u64 m   = mul2(h, h);
                u64 q   = fma2(m, B2, A2);
                u64 tg  = tanh2(mul2(h, q));
                u64 u   = fma2(tg, h, h);          // h*(1+tanh)
                d2[p]   = fma2(u, c23.x, d2[p]);   // *0.5*w2
                // psi_phase
                u64 hp  = fma2(pr2[p], c45.x, fma2(pi2[p], c45.y, c23.y));
                u64 mp  = mul2(hp, hp);
                u64 qp  = fma2(mp, B2, A2);
                u64 tp  = tanh2(mul2(hp, qp));
                u64 up  = fma2(tp, hp, hp);
                or2[p]  = fma2(up, c67.x, or2[p]);
                oi2[p]  = fma2(up, c67.y, oi2[p]);
            }
        }

        // ---- epilogue ----
        float delta[4], orr[4], oii[4];
        upk2(d2[0], delta[0], delta[1]); upk2(d2[1], delta[2], delta[3]);
        upk2(or2[0], orr[0], orr[1]);    upk2(or2[1], orr[2], orr[3]);
        upk2(oi2[0], oii[0], oii[1]);    upk2(oi2[1], oii[2], oii[3]);
        #pragma unroll
        for (int k = 0; k < 4; k++){
            float lmo  = fmaf(scale, delta[k], lm[k]);
            float nrm  = sqrt_ap(fmaf(orr[k], orr[k], oii[k]*oii[k]));
            float invn = rcp_ap(fmaxf(nrm, 1e-12f));
            float r    = __expf(lmo) * invn;
            zr[k] = fmaf(r, orr[k], zr[k]);
            zi[k] = fmaf(r, oii[k], zi[k]);
        }
    }

    ((float4*)(g_zr + base))[t] = make_float4(zr[0], zr[1], zr[2], zr[3]);
}

// ---------------------------------------------------------------------------
// Kernel C: decode  preds = gelu(feats @ op_w1 + op_b1) @ op_w2 + op_b2
// ---------------------------------------------------------------------------
__global__ void __launch_bounds__(256) decode_kernel(
    const float* __restrict__ w1, const float* __restrict__ b1,
    const float* __restrict__ w2, const float* __restrict__ b2,
    float* __restrict__ out)
{
    __shared__ float w1sh[DD*HH];   // 32 KB
    int t = threadIdx.x;
    for (int i = t; i < DD*HH; i += 256) w1sh[i] = w1[i];
    __syncthreads();

    int wid = t >> 5, lane = t & 31;
    int wg = blockIdx.x * 8 + wid;               // [0, B*S)
    int b = wg >> 10, s = wg & (SS - 1);

    const float* fp = g_zr + ((size_t)b * DD) * SS + s;
    float acc = b1[lane];
    #pragma unroll 8
    for (int d = 0; d < DD; d++){
        acc = fmaf(fp[(size_t)d * SS], w1sh[d*HH + lane], acc);
    }
    float g = gelu_exact(acc) * w2[lane];
    #pragma unroll
    for (int o = 16; o; o >>= 1) g += __shfl_down_sync(0xffffffffu, g, o);
    if (lane == 0) out[wg] = g + b2[0];
}

// ---------------------------------------------------------------------------
extern "C" void kernel_launch(void* const* d_in, const int* in_sizes, int n_in,
                              void* d_out, int out_size)
{
    const float* x     = (const float*)d_in[0];
    const float* er_w  = (const float*)d_in[1];
    const float* er_b  = (const float*)d_in[2];
    const float* ei_w  = (const float*)d_in[3];
    const float* ei_b  = (const float*)d_in[4];
    const float* pm_w1 = (const float*)d_in[5];
    const float* pm_b1 = (const float*)d_in[6];
    const float* pm_w2 = (const float*)d_in[7];
    const float* pm_b2 = (const float*)d_in[8];
    const float* pp_w1 = (const float*)d_in[9];
    const float* pp_b1 = (const float*)d_in[10];
    const float* pp_w2 = (const float*)d_in[11];
    const float* pp_b2 = (const float*)d_in[12];
    const float* mscal = (const float*)d_in[13];
    const float* op_w1 = (const float*)d_in[14];
    const float* op_b1 = (const float*)d_in[15];
    const float* op_w2 = (const float*)d_in[16];
    const float* op_b2 = (const float*)d_in[17];
    float* out = (float*)d_out;

    embed_kernel<<<BB*(SS/TS), 256>>>(x, er_w, er_b, ei_w, ei_b);
    layers_kernel<<<BB*DD, NT>>>(pm_w1, pm_b1, pm_w2, pm_b2,
                                 pp_w1, pp_b1, pp_w2, pp_b2, mscal);
    decode_kernel<<<BB*SS/8, 256>>>(op_w1, op_b1, op_w2, op_b2, out);
}

// round 3
// speedup vs baseline: 5.9002x; 2.3344x over previous
#include <cuda_runtime.h>
#include <math.h>

#define BB 8
#define SS 1024
#define DD 256
#define HH 32
#define INF 64
#define LL 4

#define MN 2048                // magnitude table entries
#define PHN 1024               // phase table entries
#define MAG_LO (-16.0f)
#define MAG_HI (6.0f)

typedef unsigned long long u64;

// scratch: z (real/imag) in [B][D][S] layout
__device__ float g_zr[BB*DD*SS];
__device__ float g_zi[BB*DD*SS];
// lookup tables
__device__ float  g_magtab[LL][MN];      // scale*delta(lm)
__device__ float2 g_phtab[LL][PHN];      // unnormalized pv_out(u)

__device__ __forceinline__ float gelu_exact(float v){
    return 0.5f * v * (1.0f + erff(v * 0.70710678118654752f));
}

// ---- f32x2 packed helpers (sm_100+) ----
__device__ __forceinline__ u64 pk2(float lo, float hi){
    u64 r; asm("mov.b64 %0, {%1, %2};" : "=l"(r) : "f"(lo), "f"(hi)); return r;
}
__device__ __forceinline__ void upk2(u64 v, float &lo, float &hi){
    asm("mov.b64 {%0, %1}, %2;" : "=f"(lo), "=f"(hi) : "l"(v));
}
__device__ __forceinline__ u64 fma2(u64 a, u64 b, u64 c){
    u64 r; asm("fma.rn.f32x2 %0, %1, %2, %3;" : "=l"(r) : "l"(a), "l"(b), "l"(c)); return r;
}
__device__ __forceinline__ float sqrt_ap(float x){
    float y; asm("sqrt.approx.f32 %0, %1;" : "=f"(y) : "f"(x)); return y;
}
__device__ __forceinline__ float rcp_ap(float x){
    float y; asm("rcp.approx.f32 %0, %1;" : "=f"(y) : "f"(x)); return y;
}

// ---------------------------------------------------------------------------
// Kernel T: build per-layer 1-D lookup tables (exact-erf GELU).
// mag table:  sd(lm) = mag_scale * (pm_b2 + sum_j gelu(w1*lm+b1)*w2)
// phase table: unnormalized pv_out at unit vector of diamond-angle u.
// ---------------------------------------------------------------------------
__global__ void __launch_bounds__(256) build_tables(
    const float* __restrict__ pm_w1, const float* __restrict__ pm_b1,
    const float* __restrict__ pm_w2, const float* __restrict__ pm_b2,
    const float* __restrict__ pp_w1, const float* __restrict__ pp_b1,
    const float* __restrict__ pp_w2, const float* __restrict__ pp_b2,
    const float* __restrict__ mag_scale)
{
    int idx = blockIdx.x * 256 + threadIdx.x;
    if (idx < LL*MN){
        int l = idx / MN, k = idx % MN;
        float lm = MAG_LO + (float)k * ((MAG_HI - MAG_LO) / (float)(MN-1));
        float acc = pm_b2[l];
        #pragma unroll 4
        for (int j = 0; j < HH; j++){
            float h = fmaf(pm_w1[l*HH+j], lm, pm_b1[l*HH+j]);
            acc = fmaf(gelu_exact(h), pm_w2[l*HH+j], acc);
        }
        g_magtab[l][k] = mag_scale[l] * acc;
        return;
    }
    idx -= LL*MN;
    if (idx < LL*PHN){
        int l = idx / PHN, k = idx % PHN;
        float uu = 4.0f * (float)k / (float)PHN;
        float x, y;
        if (uu < 1.f)      { x = 1.f-uu; y = uu;     }
        else if (uu < 2.f) { x = 1.f-uu; y = 2.f-uu; }
        else if (uu < 3.f) { x = uu-3.f; y = 2.f-uu; }
        else               { x = uu-3.f; y = uu-4.f; }
        float inv = rsqrtf(fmaf(x,x,y*y));
        float px = x*inv, py = y*inv;
        float outr = pp_b2[l*2], outi = pp_b2[l*2+1];
        #pragma unroll 4
        for (int j = 0; j < HH; j++){
            float h = fmaf(px, pp_w1[l*2*HH + j],
                      fmaf(py, pp_w1[l*2*HH + HH + j], pp_b1[l*HH+j]));
            float g = gelu_exact(h);
            outr = fmaf(g, pp_w2[(l*HH+j)*2],     outr);
            outi = fmaf(g, pp_w2[(l*HH+j)*2 + 1], outi);
        }
        g_phtab[l][k] = make_float2(outr, outi);
    }
}

// ---------------------------------------------------------------------------
// Kernel A: embed + complex rotation, write transposed [B][D][S].
// inner GEMM in packed f32x2 (pairs over s).
// ---------------------------------------------------------------------------
#define TS 16
__global__ void __launch_bounds__(256) embed_kernel(
    const float* __restrict__ x,
    const float* __restrict__ erw, const float* __restrict__ erb,
    const float* __restrict__ eiw, const float* __restrict__ eib)
{
    __shared__ float xsh[TS][INF];
    __shared__ float zshr[DD][TS+1];
    __shared__ float zshi[DD][TS+1];

    int t = threadIdx.x;                  // thread t owns d = t
    int nb_per_b = SS / TS;               // 64
    int b  = blockIdx.x / nb_per_b;
    int s0 = (blockIdx.x % nb_per_b) * TS;

    const float* xp = x + (size_t)(b*SS + s0) * INF;
    for (int i = t; i < TS*INF; i += 256) xsh[i / INF][i % INF] = xp[i];
    __syncthreads();

    int d = t;
    float br = erb[d], bi = eib[d];
    u64 ar2[TS/2], ai2[TS/2];
    #pragma unroll
    for (int p = 0; p < TS/2; p++){ ar2[p] = pk2(br, br); ai2[p] = pk2(bi, bi); }

    #pragma unroll 4
    for (int i = 0; i < INF; i++){
        float wr = erw[i*DD + d];
        float wi = eiw[i*DD + d];
        u64 wr2 = pk2(wr, wr), wi2 = pk2(wi, wi);
        #pragma unroll
        for (int p = 0; p < TS/2; p++){
            u64 xv2 = pk2(xsh[2*p][i], xsh[2*p+1][i]);   // broadcast loads
            ar2[p] = fma2(xv2, wr2, ar2[p]);
            ai2[p] = fma2(xv2, wi2, ai2[p]);
        }
    }

    float ar[TS], ai[TS];
    #pragma unroll
    for (int p = 0; p < TS/2; p++){
        upk2(ar2[p], ar[2*p], ar[2*p+1]);
        upk2(ai2[p], ai[2*p], ai[2*p+1]);
    }

    float freq = (float)exp(-9.210340371976184 * (double)d / 256.0);
    #pragma unroll
    for (int s = 0; s < TS; s++){
        float theta = (float)(s0 + s) * freq;
        float sn, cs;
        sincosf(theta, &sn, &cs);
        zshr[d][s] = ar[s]*cs - ai[s]*sn;
        zshi[d][s] = ar[s]*sn + ai[s]*cs;
    }
    __syncthreads();

    float* outr = g_zr + (size_t)b * DD * SS;
    float* outi = g_zi + (size_t)b * DD * SS;
    for (int idx = t; idx < DD*TS; idx += 256){
        int dd = idx >> 4;
        int sx = idx & (TS-1);
        outr[dd*SS + s0 + sx] = zshr[dd][sx];
        outi[dd*SS + s0 + sx] = zshi[dd][sx];
    }
}

// ---------------------------------------------------------------------------
// Kernel B: 4 causal polarizing blocks via table lookups.
// One block per (b,d); 256 threads x 4 elements; z in registers across layers.
// ---------------------------------------------------------------------------
#define NT 256
__global__ void __launch_bounds__(NT) layers_kernel()
{
    __shared__ float warp_r[8], warp_i[8];

    int t = threadIdx.x;
    size_t base = (size_t)blockIdx.x * SS;        // blockIdx = b*D + d
    float4 z4r = ((const float4*)(g_zr + base))[t];
    float4 z4i = ((const float4*)(g_zi + base))[t];
    float zr[4] = {z4r.x, z4r.y, z4r.z, z4r.w};
    float zi[4] = {z4i.x, z4i.y, z4i.z, z4i.w};

    float invc[4];
    #pragma unroll
    for (int k = 0; k < 4; k++) invc[k] = 1.0f / (float)(t*4 + k + 1);

    int lane = t & 31, wid = t >> 5;
    const float MAG_INV = (float)(MN-1) / (MAG_HI - MAG_LO);

    #pragma unroll
    for (int l = 0; l < LL; l++){
        // ---- block-wide inclusive scan of zr, zi ----
        float c0r = zr[0], c1r = c0r + zr[1], c2r = c1r + zr[2], c3r = c2r + zr[3];
        float c0i = zi[0], c1i = c0i + zi[1], c2i = c1i + zi[2], c3i = c2i + zi[3];
        float wr_ = c3r, wi_ = c3i;
        #pragma unroll
        for (int o = 1; o < 32; o <<= 1){
            float ur = __shfl_up_sync(0xffffffffu, wr_, o);
            float ui = __shfl_up_sync(0xffffffffu, wi_, o);
            if (lane >= o){ wr_ += ur; wi_ += ui; }
        }
        if (lane == 31){ warp_r[wid] = wr_; warp_i[wid] = wi_; }
        __syncthreads();
        float offr = 0.f, offi = 0.f;
        #pragma unroll
        for (int w = 0; w < 7; w++){
            if (w < wid){ offr += warp_r[w]; offi += warp_i[w]; }
        }
        __syncthreads();

        float baser = offr + wr_ - c3r;
        float basei = offi + wi_ - c3i;
        float cumr[4] = {baser + c0r, baser + c1r, baser + c2r, baser + c3r};
        float cumi[4] = {basei + c0i, basei + c1i, basei + c2i, basei + c3i};

        #pragma unroll
        for (int k = 0; k < 4; k++){
            float Ar = cumr[k]*invc[k], Ai = cumi[k]*invc[k];
            float mag = sqrt_ap(fmaf(Ar, Ar, Ai*Ai));
            float lm  = __logf(mag + 1e-6f);

            // magnitude table: sd = scale*delta(lm), linear interp, clamped
            float fi = (lm - MAG_LO) * MAG_INV;
            fi = fminf(fmaxf(fi, 0.0f), (float)(MN-1) - 1.001f);
            int   i0 = (int)fi;
            float fr = fi - (float)i0;
            float dv0 = __ldg(&g_magtab[l][i0]);
            float dv1 = __ldg(&g_magtab[l][i0+1]);
            float sd  = fmaf(fr, dv1 - dv0, dv0);

            // diamond angle u in [0,4)
            float ax = fabsf(Ar), ay = fabsf(Ai);
            float q  = ay * rcp_ap(ax + ay + 1e-30f);
            float u  = (Ar >= 0.f) ? q : 2.f - q;
            u        = (Ai >= 0.f) ? u : 4.f - u;
            float pf = u * ((float)PHN * 0.25f);
            float fl = floorf(pf);
            int   p0 = ((int)fl) & (PHN-1);
            int   p1 = (p0 + 1)  & (PHN-1);
            float prf = pf - fl;
            float2 gA = __ldg(&g_phtab[l][p0]);
            float2 gB = __ldg(&g_phtab[l][p1]);
            float gr = fmaf(prf, gB.x - gA.x, gA.x);
            float gi = fmaf(prf, gB.y - gA.y, gA.y);

            float nrm  = sqrt_ap(fmaf(gr, gr, gi*gi));
            float invn = rcp_ap(fmaxf(nrm, 1e-12f));
            float r    = __expf(lm + sd) * invn;
            zr[k] = fmaf(r, gr, zr[k]);
            zi[k] = fmaf(r, gi, zi[k]);
        }
    }

    ((float4*)(g_zr + base))[t] = make_float4(zr[0], zr[1], zr[2], zr[3]);
}

// ---------------------------------------------------------------------------
// Kernel C: decode  preds = gelu(feats @ op_w1 + op_b1) @ op_w2 + op_b2
// ---------------------------------------------------------------------------
__global__ void __launch_bounds__(256) decode_kernel(
    const float* __restrict__ w1, const float* __restrict__ b1,
    const float* __restrict__ w2, const float* __restrict__ b2,
    float* __restrict__ out)
{
    __shared__ float w1sh[DD*HH];   // 32 KB
    int t = threadIdx.x;
    for (int i = t; i < DD*HH; i += 256) w1sh[i] = w1[i];
    __syncthreads();

    int wid = t >> 5, lane = t & 31;
    int wg = blockIdx.x * 8 + wid;               // [0, B*S)
    int b = wg >> 10, s = wg & (SS - 1);

    const float* fp = g_zr + ((size_t)b * DD) * SS + s;
    float acc = b1[lane];
    #pragma unroll 8
    for (int d = 0; d < DD; d++){
        acc = fmaf(fp[(size_t)d * SS], w1sh[d*HH + lane], acc);
    }
    float g = gelu_exact(acc) * w2[lane];
    #pragma unroll
    for (int o = 16; o; o >>= 1) g += __shfl_down_sync(0xffffffffu, g, o);
    if (lane == 0) out[wg] = g + b2[0];
}

// ---------------------------------------------------------------------------
extern "C" void kernel_launch(void* const* d_in, const int* in_sizes, int n_in,
                              void* d_out, int out_size)
{
    const float* x     = (const float*)d_in[0];
    const float* er_w  = (const float*)d_in[1];
    const float* er_b  = (const float*)d_in[2];
    const float* ei_w  = (const float*)d_in[3];
    const float* ei_b  = (const float*)d_in[4];
    const float* pm_w1 = (const float*)d_in[5];
    const float* pm_b1 = (const float*)d_in[6];
    const float* pm_w2 = (const float*)d_in[7];
    const float* pm_b2 = (const float*)d_in[8];
    const float* pp_w1 = (const float*)d_in[9];
    const float* pp_b1 = (const float*)d_in[10];
    const float* pp_w2 = (const float*)d_in[11];
    const float* pp_b2 = (const float*)d_in[12];
    const float* mscal = (const float*)d_in[13];
    const float* op_w1 = (const float*)d_in[14];
    const float* op_b1 = (const float*)d_in[15];
    const float* op_w2 = (const float*)d_in[16];
    const float* op_b2 = (const float*)d_in[17];
    float* out = (float*)d_out;

    build_tables<<<(LL*(MN+PHN) + 255)/256, 256>>>(
        pm_w1, pm_b1, pm_w2, pm_b2, pp_w1, pp_b1, pp_w2, pp_b2, mscal);
    embed_kernel<<<BB*(SS/TS), 256>>>(x, er_w, er_b, ei_w, ei_b);
    layers_kernel<<<BB*DD, NT>>>();
    decode_kernel<<<BB*SS/8, 256>>>(op_w1, op_b1, op_w2, op_b2, out);
}

// round 4
// speedup vs baseline: 8.2593x; 1.3998x over previous
#include <cuda_runtime.h>
#include <math.h>

#define BB 8
#define SS 1024
#define DD 256
#define HH 32
#define INF 64
#define LL 4

#define MN 2048                // magnitude table entries
#define PHN 1024               // phase table entries
#define MAG_LO (-16.0f)
#define MAG_HI (6.0f)

typedef unsigned long long u64;

// scratch: z (real/imag) in [B][D][S] layout
__device__ float g_zr[BB*DD*SS];
__device__ float g_zi[BB*DD*SS];
// lookup tables
__device__ float  g_magtab[LL][MN];      // scale*delta(lm)
__device__ float2 g_phtab[LL][PHN];      // unnormalized pv_out(u)

__device__ __forceinline__ float gelu_exact(float v){
    return 0.5f * v * (1.0f + erff(v * 0.70710678118654752f));
}

// ---- f32x2 packed helpers (sm_100+) ----
__device__ __forceinline__ u64 pk2(float lo, float hi){
    u64 r; asm("mov.b64 %0, {%1, %2};" : "=l"(r) : "f"(lo), "f"(hi)); return r;
}
__device__ __forceinline__ void upk2(u64 v, float &lo, float &hi){
    asm("mov.b64 {%0, %1}, %2;" : "=f"(lo), "=f"(hi) : "l"(v));
}
__device__ __forceinline__ u64 fma2(u64 a, u64 b, u64 c){
    u64 r; asm("fma.rn.f32x2 %0, %1, %2, %3;" : "=l"(r) : "l"(a), "l"(b), "l"(c)); return r;
}
__device__ __forceinline__ float sqrt_ap(float x){
    float y; asm("sqrt.approx.f32 %0, %1;" : "=f"(y) : "f"(x)); return y;
}
__device__ __forceinline__ float rcp_ap(float x){
    float y; asm("rcp.approx.f32 %0, %1;" : "=f"(y) : "f"(x)); return y;
}

// ---------------------------------------------------------------------------
// Kernel T: build per-layer 1-D lookup tables (exact-erf GELU).
// ---------------------------------------------------------------------------
__global__ void __launch_bounds__(256) build_tables(
    const float* __restrict__ pm_w1, const float* __restrict__ pm_b1,
    const float* __restrict__ pm_w2, const float* __restrict__ pm_b2,
    const float* __restrict__ pp_w1, const float* __restrict__ pp_b1,
    const float* __restrict__ pp_w2, const float* __restrict__ pp_b2,
    const float* __restrict__ mag_scale)
{
    int idx = blockIdx.x * 256 + threadIdx.x;
    if (idx < LL*MN){
        int l = idx / MN, k = idx % MN;
        float lm = MAG_LO + (float)k * ((MAG_HI - MAG_LO) / (float)(MN-1));
        float acc = pm_b2[l];
        #pragma unroll 4
        for (int j = 0; j < HH; j++){
            float h = fmaf(pm_w1[l*HH+j], lm, pm_b1[l*HH+j]);
            acc = fmaf(gelu_exact(h), pm_w2[l*HH+j], acc);
        }
        g_magtab[l][k] = mag_scale[l] * acc;
        return;
    }
    idx -= LL*MN;
    if (idx < LL*PHN){
        int l = idx / PHN, k = idx % PHN;
        float uu = 4.0f * (float)k / (float)PHN;
        float x, y;
        if (uu < 1.f)      { x = 1.f-uu; y = uu;     }
        else if (uu < 2.f) { x = 1.f-uu; y = 2.f-uu; }
        else if (uu < 3.f) { x = uu-3.f; y = 2.f-uu; }
        else               { x = uu-3.f; y = uu-4.f; }
        float inv = rsqrtf(fmaf(x,x,y*y));
        float px = x*inv, py = y*inv;
        float outr = pp_b2[l*2], outi = pp_b2[l*2+1];
        #pragma unroll 4
        for (int j = 0; j < HH; j++){
            float h = fmaf(px, pp_w1[l*2*HH + j],
                      fmaf(py, pp_w1[l*2*HH + HH + j], pp_b1[l*HH+j]));
            float g = gelu_exact(h);
            outr = fmaf(g, pp_w2[(l*HH+j)*2],     outr);
            outi = fmaf(g, pp_w2[(l*HH+j)*2 + 1], outi);
        }
        g_phtab[l][k] = make_float2(outr, outi);
    }
}

// ---------------------------------------------------------------------------
// Kernel A: embed + complex rotation, write transposed [B][D][S].
// x tile stored transposed in shared (stride 18) -> single LDS.64 per pair.
// sincos via 2 sincosf + rotation recurrence.
// ---------------------------------------------------------------------------
#define TS 16
#define XST 18
__global__ void __launch_bounds__(256) embed_kernel(
    const float* __restrict__ x,
    const float* __restrict__ erw, const float* __restrict__ erb,
    const float* __restrict__ eiw, const float* __restrict__ eib)
{
    __shared__ float xsh[INF*XST];        // [i][s], stride 18
    __shared__ float zshr[DD][TS+1];
    __shared__ float zshi[DD][TS+1];

    int t = threadIdx.x;                  // thread t owns d = t
    int nb_per_b = SS / TS;               // 64
    int b  = blockIdx.x / nb_per_b;
    int s0 = (blockIdx.x % nb_per_b) * TS;

    const float* xp = x + (size_t)(b*SS + s0) * INF;
    for (int e = t; e < TS*INF; e += 256){
        int s = e >> 6, i = e & 63;
        xsh[i*XST + s] = xp[e];
    }
    __syncthreads();

    int d = t;
    float br = erb[d], bi = eib[d];
    u64 ar2[TS/2], ai2[TS/2];
    #pragma unroll
    for (int p = 0; p < TS/2; p++){ ar2[p] = pk2(br, br); ai2[p] = pk2(bi, bi); }

    #pragma unroll 4
    for (int i = 0; i < INF; i++){
        float wr = erw[i*DD + d];
        float wi = eiw[i*DD + d];
        u64 wr2 = pk2(wr, wr), wi2 = pk2(wi, wi);
        const u64* xr = (const u64*)(xsh + i*XST);
        #pragma unroll
        for (int p = 0; p < TS/2; p++){
            u64 xv2 = xr[p];               // broadcast LDS.64
            ar2[p] = fma2(xv2, wr2, ar2[p]);
            ai2[p] = fma2(xv2, wi2, ai2[p]);
        }
    }

    float ar[TS], ai[TS];
    #pragma unroll
    for (int p = 0; p < TS/2; p++){
        upk2(ar2[p], ar[2*p], ar[2*p+1]);
        upk2(ai2[p], ai[2*p], ai[2*p+1]);
    }

    float freq = (float)exp(-9.210340371976184 * (double)d / 256.0);
    float sn, cs, sdl, cdl;
    sincosf((float)s0 * freq, &sn, &cs);
    sincosf(freq, &sdl, &cdl);
    #pragma unroll
    for (int s = 0; s < TS; s++){
        zshr[d][s] = ar[s]*cs - ai[s]*sn;
        zshi[d][s] = ar[s]*sn + ai[s]*cs;
        float cn = cs*cdl - sn*sdl;
        float sx = sn*cdl + cs*sdl;
        cs = cn; sn = sx;
    }
    __syncthreads();

    float* outr = g_zr + (size_t)b * DD * SS;
    float* outi = g_zi + (size_t)b * DD * SS;
    for (int idx = t; idx < DD*TS; idx += 256){
        int dd = idx >> 4;
        int sx = idx & (TS-1);
        outr[dd*SS + s0 + sx] = zshr[dd][sx];
        outi[dd*SS + s0 + sx] = zshi[dd][sx];
    }
}

// ---------------------------------------------------------------------------
// Kernel B: 4 causal polarizing blocks via table lookups.
// ---------------------------------------------------------------------------
#define NT 256
__global__ void __launch_bounds__(NT) layers_kernel()
{
    __shared__ float warp_r[8], warp_i[8];

    int t = threadIdx.x;
    size_t base = (size_t)blockIdx.x * SS;        // blockIdx = b*D + d
    float4 z4r = ((const float4*)(g_zr + base))[t];
    float4 z4i = ((const float4*)(g_zi + base))[t];
    float zr[4] = {z4r.x, z4r.y, z4r.z, z4r.w};
    float zi[4] = {z4i.x, z4i.y, z4i.z, z4i.w};

    float invc[4];
    #pragma unroll
    for (int k = 0; k < 4; k++) invc[k] = 1.0f / (float)(t*4 + k + 1);

    int lane = t & 31, wid = t >> 5;
    const float MAG_INV = (float)(MN-1) / (MAG_HI - MAG_LO);

    #pragma unroll
    for (int l = 0; l < LL; l++){
        // ---- block-wide inclusive scan of zr, zi ----
        float c0r = zr[0], c1r = c0r + zr[1], c2r = c1r + zr[2], c3r = c2r + zr[3];
        float c0i = zi[0], c1i = c0i + zi[1], c2i = c1i + zi[2], c3i = c2i + zi[3];
        float wr_ = c3r, wi_ = c3i;
        #pragma unroll
        for (int o = 1; o < 32; o <<= 1){
            float ur = __shfl_up_sync(0xffffffffu, wr_, o);
            float ui = __shfl_up_sync(0xffffffffu, wi_, o);
            if (lane >= o){ wr_ += ur; wi_ += ui; }
        }
        if (lane == 31){ warp_r[wid] = wr_; warp_i[wid] = wi_; }
        __syncthreads();
        float offr = 0.f, offi = 0.f;
        #pragma unroll
        for (int w = 0; w < 7; w++){
            if (w < wid){ offr += warp_r[w]; offi += warp_i[w]; }
        }
        __syncthreads();

        float baser = offr + wr_ - c3r;
        float basei = offi + wi_ - c3i;
        float cumr[4] = {baser + c0r, baser + c1r, baser + c2r, baser + c3r};
        float cumi[4] = {basei + c0i, basei + c1i, basei + c2i, basei + c3i};

        #pragma unroll
        for (int k = 0; k < 4; k++){
            float Ar = cumr[k]*invc[k], Ai = cumi[k]*invc[k];
            float mag = sqrt_ap(fmaf(Ar, Ar, Ai*Ai));
            float lm  = __logf(mag + 1e-6f);

            // magnitude table: sd = scale*delta(lm), linear interp, clamped
            float fi = (lm - MAG_LO) * MAG_INV;
            fi = fminf(fmaxf(fi, 0.0f), (float)(MN-1) - 1.001f);
            int   i0 = (int)fi;
            float fr = fi - (float)i0;
            float dv0 = __ldg(&g_magtab[l][i0]);
            float dv1 = __ldg(&g_magtab[l][i0+1]);
            float sd  = fmaf(fr, dv1 - dv0, dv0);

            // diamond angle u in [0,4)
            float ax = fabsf(Ar), ay = fabsf(Ai);
            float q  = ay * rcp_ap(ax + ay + 1e-30f);
            float u  = (Ar >= 0.f) ? q : 2.f - q;
            u        = (Ai >= 0.f) ? u : 4.f - u;
            float pf = u * ((float)PHN * 0.25f);
            float fl = floorf(pf);
            int   p0 = ((int)fl) & (PHN-1);
            int   p1 = (p0 + 1)  & (PHN-1);
            float prf = pf - fl;
            float2 gA = __ldg(&g_phtab[l][p0]);
            float2 gB = __ldg(&g_phtab[l][p1]);
            float gr = fmaf(prf, gB.x - gA.x, gA.x);
            float gi = fmaf(prf, gB.y - gA.y, gA.y);

            float nrm  = sqrt_ap(fmaf(gr, gr, gi*gi));
            float invn = rcp_ap(fmaxf(nrm, 1e-12f));
            float r    = __expf(lm + sd) * invn;
            zr[k] = fmaf(r, gr, zr[k]);
            zi[k] = fmaf(r, gi, zi[k]);
        }
    }

    ((float4*)(g_zr + base))[t] = make_float4(zr[0], zr[1], zr[2], zr[3]);
}

// ---------------------------------------------------------------------------
// Kernel C: decode as tiled GEMV. Block = 64 s-values, 256 threads.
// Thread (grp, s_loc): 32 hidden accumulators over 64-d slice.
// Shared buffer reused: first 32KB w1 tile, then partial-sum matrix.
// ---------------------------------------------------------------------------
#define DBS 64
__global__ void __launch_bounds__(256) decode_kernel(
    const float* __restrict__ w1, const float* __restrict__ b1,
    const float* __restrict__ w2, const float* __restrict__ b2,
    float* __restrict__ out)
{
    __shared__ float sbuf[DD*HH];   // 32 KB: w1 tile, later partials [4][DBS][HH]
    int t = threadIdx.x;
    for (int i = t; i < DD*HH; i += 256) sbuf[i] = w1[i];
    __syncthreads();

    int s_loc = t & (DBS-1);
    int grp   = t >> 6;                          // 0..3
    int sg    = blockIdx.x * DBS + s_loc;
    int b = sg >> 10, s = sg & (SS-1);
    const float* fp = g_zr + (size_t)b * DD * SS + s;

    float acc[HH];
    #pragma unroll
    for (int h = 0; h < HH; h++) acc[h] = 0.f;

    int d0 = grp * 64;
    #pragma unroll 4
    for (int dd = 0; dd < 64; dd++){
        int d = d0 + dd;
        float f = fp[(size_t)d * SS];            // coalesced 128B across warp
        const float4* wrow = (const float4*)(sbuf + d*HH);
        #pragma unroll
        for (int qq = 0; qq < 8; qq++){
            float4 w4 = wrow[qq];                // broadcast LDS.128
            acc[qq*4+0] = fmaf(f, w4.x, acc[qq*4+0]);
            acc[qq*4+1] = fmaf(f, w4.y, acc[qq*4+1]);
            acc[qq*4+2] = fmaf(f, w4.z, acc[qq*4+2]);
            acc[qq*4+3] = fmaf(f, w4.w, acc[qq*4+3]);
        }
    }
    __syncthreads();   // everyone done reading w1 tile; sbuf becomes partials

    float4* rp = (float4*)(sbuf + (grp*DBS + s_loc)*HH);
    #pragma unroll
    for (int qq = 0; qq < 8; qq++)
        rp[qq] = make_float4(acc[qq*4+0], acc[qq*4+1], acc[qq*4+2], acc[qq*4+3]);
    __syncthreads();

    // final: warp w handles 8 s-values; lane = hidden unit
    int wid = t >> 5, lane = t & 31;
    float bb1 = b1[lane], ww2 = w2[lane], bb2 = b2[0];
    #pragma unroll
    for (int si = wid*8; si < wid*8 + 8; si++){
        float hsum = bb1;
        #pragma unroll
        for (int g = 0; g < 4; g++)
            hsum += sbuf[(g*DBS + si)*HH + lane];
        float y = gelu_exact(hsum) * ww2;
        #pragma unroll
        for (int o = 16; o; o >>= 1) y += __shfl_down_sync(0xffffffffu, y, o);
        if (lane == 0) out[blockIdx.x * DBS + si] = y + bb2;
    }
}

// ---------------------------------------------------------------------------
extern "C" void kernel_launch(void* const* d_in, const int* in_sizes, int n_in,
                              void* d_out, int out_size)
{
    const float* x     = (const float*)d_in[0];
    const float* er_w  = (const float*)d_in[1];
    const float* er_b  = (const float*)d_in[2];
    const float* ei_w  = (const float*)d_in[3];
    const float* ei_b  = (const float*)d_in[4];
    const float* pm_w1 = (const float*)d_in[5];
    const float* pm_b1 = (const float*)d_in[6];
    const float* pm_w2 = (const float*)d_in[7];
    const float* pm_b2 = (const float*)d_in[8];
    const float* pp_w1 = (const float*)d_in[9];
    const float* pp_b1 = (const float*)d_in[10];
    const float* pp_w2 = (const float*)d_in[11];
    const float* pp_b2 = (const float*)d_in[12];
    const float* mscal = (const float*)d_in[13];
    const float* op_w1 = (const float*)d_in[14];
    const float* op_b1 = (const float*)d_in[15];
    const float* op_w2 = (const float*)d_in[16];
    const float* op_b2 = (const float*)d_in[17];
    float* out = (float*)d_out;

    build_tables<<<(LL*(MN+PHN) + 255)/256, 256>>>(
        pm_w1, pm_b1, pm_w2, pm_b2, pp_w1, pp_b1, pp_w2, pp_b2, mscal);
    embed_kernel<<<BB*(SS/TS), 256>>>(x, er_w, er_b, ei_w, ei_b);
    layers_kernel<<<BB*DD, NT>>>();
    decode_kernel<<<BB*SS/DBS, 256>>>(op_w1, op_b1, op_w2, op_b2, out);
}

// round 5
// speedup vs baseline: 8.7596x; 1.0606x over previous
#include <cuda_runtime.h>
#include <math.h>

#define BB 8
#define SS 1024
#define DD 256
#define HH 32
#define INF 64
#define LL 4

#define MN 2048                // magnitude table entries
#define PHN 1024               // phase table entries
#define MAG_LO (-16.0f)
#define MAG_HI (6.0f)

typedef unsigned long long u64;

// scratch: z (real/imag) in [B][D][S] layout
__device__ float g_zr[BB*DD*SS];
__device__ float g_zi[BB*DD*SS];
// lookup tables
__device__ float  g_magtab[LL][MN];      // scale*delta(lm)
__device__ float2 g_phtab[LL][PHN];      // unnormalized pv_out(u)

__device__ __forceinline__ float gelu_exact(float v){
    return 0.5f * v * (1.0f + erff(v * 0.70710678118654752f));
}

// ---- f32x2 packed helpers (sm_100+) ----
__device__ __forceinline__ u64 pk2(float lo, float hi){
    u64 r; asm("mov.b64 %0, {%1, %2};" : "=l"(r) : "f"(lo), "f"(hi)); return r;
}
__device__ __forceinline__ void upk2(u64 v, float &lo, float &hi){
    asm("mov.b64 {%0, %1}, %2;" : "=f"(lo), "=f"(hi) : "l"(v));
}
__device__ __forceinline__ u64 fma2(u64 a, u64 b, u64 c){
    u64 r; asm("fma.rn.f32x2 %0, %1, %2, %3;" : "=l"(r) : "l"(a), "l"(b), "l"(c)); return r;
}
__device__ __forceinline__ float rcp_ap(float x){
    float y; asm("rcp.approx.f32 %0, %1;" : "=f"(y) : "f"(x)); return y;
}
__device__ __forceinline__ float rsqrt_ap(float x){
    float y; asm("rsqrt.approx.f32 %0, %1;" : "=f"(y) : "f"(x)); return y;
}

// ---------------------------------------------------------------------------
// Kernel T: build per-layer 1-D lookup tables (exact-erf GELU).
// ---------------------------------------------------------------------------
__global__ void __launch_bounds__(256) build_tables(
    const float* __restrict__ pm_w1, const float* __restrict__ pm_b1,
    const float* __restrict__ pm_w2, const float* __restrict__ pm_b2,
    const float* __restrict__ pp_w1, const float* __restrict__ pp_b1,
    const float* __restrict__ pp_w2, const float* __restrict__ pp_b2,
    const float* __restrict__ mag_scale)
{
    int idx = blockIdx.x * 256 + threadIdx.x;
    if (idx < LL*MN){
        int l = idx / MN, k = idx % MN;
        float lm = MAG_LO + (float)k * ((MAG_HI - MAG_LO) / (float)(MN-1));
        float acc = pm_b2[l];
        #pragma unroll 4
        for (int j = 0; j < HH; j++){
            float h = fmaf(pm_w1[l*HH+j], lm, pm_b1[l*HH+j]);
            acc = fmaf(gelu_exact(h), pm_w2[l*HH+j], acc);
        }
        g_magtab[l][k] = mag_scale[l] * acc;
        return;
    }
    idx -= LL*MN;
    if (idx < LL*PHN){
        int l = idx / PHN, k = idx % PHN;
        float uu = 4.0f * (float)k / (float)PHN;
        float x, y;
        if (uu < 1.f)      { x = 1.f-uu; y = uu;     }
        else if (uu < 2.f) { x = 1.f-uu; y = 2.f-uu; }
        else if (uu < 3.f) { x = uu-3.f; y = 2.f-uu; }
        else               { x = uu-3.f; y = uu-4.f; }
        float inv = rsqrtf(fmaf(x,x,y*y));
        float px = x*inv, py = y*inv;
        float outr = pp_b2[l*2], outi = pp_b2[l*2+1];
        #pragma unroll 4
        for (int j = 0; j < HH; j++){
            float h = fmaf(px, pp_w1[l*2*HH + j],
                      fmaf(py, pp_w1[l*2*HH + HH + j], pp_b1[l*HH+j]));
            float g = gelu_exact(h);
            outr = fmaf(g, pp_w2[(l*HH+j)*2],     outr);
            outi = fmaf(g, pp_w2[(l*HH+j)*2 + 1], outi);
        }
        g_phtab[l][k] = make_float2(outr, outi);
    }
}

// ---------------------------------------------------------------------------
// Kernel A: embed + complex rotation, write transposed [B][D][S].
// ---------------------------------------------------------------------------
#define TS 16
#define XST 18
__global__ void __launch_bounds__(256) embed_kernel(
    const float* __restrict__ x,
    const float* __restrict__ erw, const float* __restrict__ erb,
    const float* __restrict__ eiw, const float* __restrict__ eib)
{
    __shared__ float xsh[INF*XST];        // [i][s], stride 18
    __shared__ float zshr[DD][TS+1];
    __shared__ float zshi[DD][TS+1];

    int t = threadIdx.x;                  // thread t owns d = t
    int nb_per_b = SS / TS;               // 64
    int b  = blockIdx.x / nb_per_b;
    int s0 = (blockIdx.x % nb_per_b) * TS;

    const float* xp = x + (size_t)(b*SS + s0) * INF;
    for (int e = t; e < TS*INF; e += 256){
        int s = e >> 6, i = e & 63;
        xsh[i*XST + s] = xp[e];
    }
    __syncthreads();

    int d = t;
    float br = erb[d], bi = eib[d];
    u64 ar2[TS/2], ai2[TS/2];
    #pragma unroll
    for (int p = 0; p < TS/2; p++){ ar2[p] = pk2(br, br); ai2[p] = pk2(bi, bi); }

    #pragma unroll 4
    for (int i = 0; i < INF; i++){
        float wr = erw[i*DD + d];
        float wi = eiw[i*DD + d];
        u64 wr2 = pk2(wr, wr), wi2 = pk2(wi, wi);
        const u64* xr = (const u64*)(xsh + i*XST);
        #pragma unroll
        for (int p = 0; p < TS/2; p++){
            u64 xv2 = xr[p];               // broadcast LDS.64
            ar2[p] = fma2(xv2, wr2, ar2[p]);
            ai2[p] = fma2(xv2, wi2, ai2[p]);
        }
    }

    float freq = (float)exp(-9.210340371976184 * (double)d / 256.0);
    float sn, cs, sdl, cdl;
    sincosf((float)s0 * freq, &sn, &cs);
    sincosf(freq, &sdl, &cdl);
    #pragma unroll
    for (int p = 0; p < TS/2; p++){
        float a0, a1, q0, q1;
        upk2(ar2[p], a0, a1);
        upk2(ai2[p], q0, q1);
        zshr[d][2*p]   = a0*cs - q0*sn;
        zshi[d][2*p]   = a0*sn + q0*cs;
        float cn = cs*cdl - sn*sdl;
        float sx = sn*cdl + cs*sdl;
        cs = cn; sn = sx;
        zshr[d][2*p+1] = a1*cs - q1*sn;
        zshi[d][2*p+1] = a1*sn + q1*cs;
        cn = cs*cdl - sn*sdl;
        sx = sn*cdl + cs*sdl;
        cs = cn; sn = sx;
    }
    __syncthreads();

    float* outr = g_zr + (size_t)b * DD * SS;
    float* outi = g_zi + (size_t)b * DD * SS;
    for (int idx = t; idx < DD*TS; idx += 256){
        int dd = idx >> 4;
        int sx = idx & (TS-1);
        outr[dd*SS + s0 + sx] = zshr[dd][sx];
        outi[dd*SS + s0 + sx] = zshi[dd][sx];
    }
}

// ---------------------------------------------------------------------------
// Kernel B: 4 causal polarizing blocks via table lookups.
// ---------------------------------------------------------------------------
#define NT 256
__global__ void __launch_bounds__(NT) layers_kernel()
{
    __shared__ float warp_r[LL][8], warp_i[LL][8];

    int t = threadIdx.x;
    size_t base = (size_t)blockIdx.x * SS;        // blockIdx = b*D + d
    float4 z4r = ((const float4*)(g_zr + base))[t];
    float4 z4i = ((const float4*)(g_zi + base))[t];
    float zr[4] = {z4r.x, z4r.y, z4r.z, z4r.w};
    float zi[4] = {z4i.x, z4i.y, z4i.z, z4i.w};

    float invc[4];
    #pragma unroll
    for (int k = 0; k < 4; k++) invc[k] = 1.0f / (float)(t*4 + k + 1);

    int lane = t & 31, wid = t >> 5;
    const float MAG_INV = (float)(MN-1) / (MAG_HI - MAG_LO);

    #pragma unroll
    for (int l = 0; l < LL; l++){
        // ---- block-wide inclusive scan of zr, zi ----
        float c0r = zr[0], c1r = c0r + zr[1], c2r = c1r + zr[2], c3r = c2r + zr[3];
        float c0i = zi[0], c1i = c0i + zi[1], c2i = c1i + zi[2], c3i = c2i + zi[3];
        float wr_ = c3r, wi_ = c3i;
        #pragma unroll
        for (int o = 1; o < 32; o <<= 1){
            float ur = __shfl_up_sync(0xffffffffu, wr_, o);
            float ui = __shfl_up_sync(0xffffffffu, wi_, o);
            if (lane >= o){ wr_ += ur; wi_ += ui; }
        }
        if (lane == 31){ warp_r[l][wid] = wr_; warp_i[l][wid] = wi_; }
        __syncthreads();                  // per-layer buffer: single barrier
        float offr = 0.f, offi = 0.f;
        #pragma unroll
        for (int w = 0; w < 7; w++){
            if (w < wid){ offr += warp_r[l][w]; offi += warp_i[l][w]; }
        }

        float baser = offr + wr_ - c3r;
        float basei = offi + wi_ - c3i;
        float cumr[4] = {baser + c0r, baser + c1r, baser + c2r, baser + c3r};
        float cumi[4] = {basei + c0i, basei + c1i, basei + c2i, basei + c3i};

        #pragma unroll
        for (int k = 0; k < 4; k++){
            float Ar = cumr[k]*invc[k], Ai = cumi[k]*invc[k];
            float m2 = fmaf(Ar, Ar, Ai*Ai);
            float lm = 0.5f * __logf(m2 + 1e-12f);

            // magnitude table: sd = scale*delta(lm), linear interp, clamped
            float fi = (lm - MAG_LO) * MAG_INV;
            fi = fminf(fmaxf(fi, 0.0f), (float)(MN-1) - 1.001f);
            int   i0 = (int)fi;
            float fr = fi - (float)i0;
            float dv0 = __ldg(&g_magtab[l][i0]);
            float dv1 = __ldg(&g_magtab[l][i0+1]);
            float sd  = fmaf(fr, dv1 - dv0, dv0);

            // diamond angle u in [0,4)
            float ax = fabsf(Ar), ay = fabsf(Ai);
            float q  = ay * rcp_ap(ax + ay + 1e-30f);
            float u  = (Ar >= 0.f) ? q : 2.f - q;
            u        = (Ai >= 0.f) ? u : 4.f - u;
            float pf = u * ((float)PHN * 0.25f);
            float fl = floorf(pf);
            int   p0 = ((int)fl) & (PHN-1);
            int   p1 = (p0 + 1)  & (PHN-1);
            float prf = pf - fl;
            float2 gA = __ldg(&g_phtab[l][p0]);
            float2 gB = __ldg(&g_phtab[l][p1]);
            float gr = fmaf(prf, gB.x - gA.x, gA.x);
            float gi = fmaf(prf, gB.y - gA.y, gA.y);

            float nrm2 = fmaf(gr, gr, gi*gi);
            float invn = rsqrt_ap(fmaxf(nrm2, 1e-24f));
            float r    = __expf(lm + sd) * invn;
            zr[k] = fmaf(r, gr, zr[k]);
            zi[k] = fmaf(r, gi, zi[k]);
        }
    }

    ((float4*)(g_zr + base))[t] = make_float4(zr[0], zr[1], zr[2], zr[3]);
}

// ---------------------------------------------------------------------------
// Kernel C: decode as tiled GEMV. Block = 32 s-values, 256 threads.
// 8 d-groups of 32 d; f32x2 packed hidden accumulators.
// ---------------------------------------------------------------------------
#define DBS 32
__global__ void __launch_bounds__(256) decode_kernel(
    const float* __restrict__ w1, const float* __restrict__ b1,
    const float* __restrict__ w2, const float* __restrict__ b2,
    float* __restrict__ out)
{
    __shared__ float sbuf[DD*HH];   // 32 KB: w1 tile, later partials [8][DBS][HH]
    int t = threadIdx.x;
    const float4* w1v = (const float4*)w1;
    float4* sv = (float4*)sbuf;
    for (int i = t; i < DD*HH/4; i += 256) sv[i] = w1v[i];
    __syncthreads();

    int s_loc = t & (DBS-1);
    int grp   = t >> 5;                          // 0..7, 32 d each
    int sg    = blockIdx.x * DBS + s_loc;
    int b = sg >> 10, s = sg & (SS-1);
    const float* fp = g_zr + (size_t)b * DD * SS + (size_t)(grp*32) * SS + s;

    u64 acc[16];
    #pragma unroll
    for (int h = 0; h < 16; h++) acc[h] = 0ull;

    #pragma unroll 4
    for (int dd = 0; dd < 32; dd++){
        float f = fp[(size_t)dd * SS];           // coalesced 128B per warp
        u64 f2 = pk2(f, f);
        const ulonglong2* wrow = (const ulonglong2*)(sbuf + (grp*32 + dd)*HH);
        #pragma unroll
        for (int q = 0; q < 8; q++){
            ulonglong2 wv = wrow[q];             // broadcast LDS.128 = 2 h-pairs
            acc[2*q]   = fma2(f2, wv.x, acc[2*q]);
            acc[2*q+1] = fma2(f2, wv.y, acc[2*q+1]);
        }
    }
    __syncthreads();   // done reading w1 tile; sbuf becomes partials

    ulonglong2* rp = (ulonglong2*)(sbuf + (grp*DBS + s_loc)*HH);
    #pragma unroll
    for (int q = 0; q < 8; q++) rp[q] = make_ulonglong2(acc[2*q], acc[2*q+1]);
    __syncthreads();

    // final: warp wid handles 4 s-values; lane = hidden unit
    int wid = t >> 5, lane = t & 31;
    float bb1 = b1[lane], ww2 = w2[lane], bb2 = b2[0];
    #pragma unroll
    for (int si = wid*4; si < wid*4 + 4; si++){
        float hsum = bb1;
        #pragma unroll
        for (int g = 0; g < 8; g++)
            hsum += sbuf[(g*DBS + si)*HH + lane];
        float y = gelu_exact(hsum) * ww2;
        #pragma unroll
        for (int o = 16; o; o >>= 1) y += __shfl_down_sync(0xffffffffu, y, o);
        if (lane == 0) out[blockIdx.x * DBS + si] = y + bb2;
    }
}

// ---------------------------------------------------------------------------
extern "C" void kernel_launch(void* const* d_in, const int* in_sizes, int n_in,
                              void* d_out, int out_size)
{
    const float* x     = (const float*)d_in[0];
    const float* er_w  = (const float*)d_in[1];
    const float* er_b  = (const float*)d_in[2];
    const float* ei_w  = (const float*)d_in[3];
    const float* ei_b  = (const float*)d_in[4];
    const float* pm_w1 = (const float*)d_in[5];
    const float* pm_b1 = (const float*)d_in[6];
    const float* pm_w2 = (const float*)d_in[7];
    const float* pm_b2 = (const float*)d_in[8];
    const float* pp_w1 = (const float*)d_in[9];
    const float* pp_b1 = (const float*)d_in[10];
    const float* pp_w2 = (const float*)d_in[11];
    const float* pp_b2 = (const float*)d_in[12];
    const float* mscal = (const float*)d_in[13];
    const float* op_w1 = (const float*)d_in[14];
    const float* op_b1 = (const float*)d_in[15];
    const float* op_w2 = (const float*)d_in[16];
    const float* op_b2 = (const float*)d_in[17];
    float* out = (float*)d_out;

    build_tables<<<(LL*(MN+PHN) + 255)/256, 256>>>(
        pm_w1, pm_b1, pm_w2, pm_b2, pp_w1, pp_b1, pp_w2, pp_b2, mscal);
    embed_kernel<<<BB*(SS/TS), 256>>>(x, er_w, er_b, ei_w, ei_b);
    layers_kernel<<<BB*DD, NT>>>();
    decode_kernel<<<BB*SS/DBS, 256>>>(op_w1, op_b1, op_w2, op_b2, out);
}

// round 6
// speedup vs baseline: 9.3244x; 1.0645x over previous
#include <cuda_runtime.h>
#include <math.h>

#define BB 8
#define SS 1024
#define DD 256
#define HH 32
#define INF 64
#define LL 4

#define MN 2048                // magnitude table entries
#define PHN 1024               // phase table entries
#define MAG_LO (-16.0f)
#define MAG_HI (6.0f)

typedef unsigned long long u64;

// scratch: z (real/imag) in [B][D][S] layout
__device__ float g_zr[BB*DD*SS];
__device__ float g_zi[BB*DD*SS];
// lookup tables
__device__ float  g_magtab[LL][MN];      // scale*delta(lm)
__device__ float2 g_phtab[LL][PHN];      // unnormalized pv_out(u)

__device__ __forceinline__ float gelu_exact(float v){
    return 0.5f * v * (1.0f + erff(v * 0.70710678118654752f));
}

// ---- f32x2 packed helpers (sm_100+) ----
__device__ __forceinline__ u64 pk2(float lo, float hi){
    u64 r; asm("mov.b64 %0, {%1, %2};" : "=l"(r) : "f"(lo), "f"(hi)); return r;
}
__device__ __forceinline__ void upk2(u64 v, float &lo, float &hi){
    asm("mov.b64 {%0, %1}, %2;" : "=f"(lo), "=f"(hi) : "l"(v));
}
__device__ __forceinline__ u64 fma2(u64 a, u64 b, u64 c){
    u64 r; asm("fma.rn.f32x2 %0, %1, %2, %3;" : "=l"(r) : "l"(a), "l"(b), "l"(c)); return r;
}
__device__ __forceinline__ float rcp_ap(float x){
    float y; asm("rcp.approx.f32 %0, %1;" : "=f"(y) : "f"(x)); return y;
}
__device__ __forceinline__ float rsqrt_ap(float x){
    float y; asm("rsqrt.approx.f32 %0, %1;" : "=f"(y) : "f"(x)); return y;
}

// ---------------------------------------------------------------------------
// Kernel T: build per-layer 1-D lookup tables. Warp per entry, lane = hidden j.
// ---------------------------------------------------------------------------
__global__ void __launch_bounds__(256) build_tables(
    const float* __restrict__ pm_w1, const float* __restrict__ pm_b1,
    const float* __restrict__ pm_w2, const float* __restrict__ pm_b2,
    const float* __restrict__ pp_w1, const float* __restrict__ pp_b1,
    const float* __restrict__ pp_w2, const float* __restrict__ pp_b2,
    const float* __restrict__ mag_scale)
{
    int wgid = blockIdx.x * 8 + (threadIdx.x >> 5);   // warp-entry id
    int j    = threadIdx.x & 31;                      // hidden unit
    if (wgid < LL*MN){
        int l = wgid / MN, k = wgid % MN;
        float lm = MAG_LO + (float)k * ((MAG_HI - MAG_LO) / (float)(MN-1));
        float h  = fmaf(pm_w1[l*HH+j], lm, pm_b1[l*HH+j]);
        float v  = gelu_exact(h) * pm_w2[l*HH+j];
        #pragma unroll
        for (int o = 16; o; o >>= 1) v += __shfl_down_sync(0xffffffffu, v, o);
        if (j == 0) g_magtab[l][k] = mag_scale[l] * (v + pm_b2[l]);
        return;
    }
    wgid -= LL*MN;
    if (wgid < LL*PHN){
        int l = wgid / PHN, k = wgid % PHN;
        float uu = 4.0f * (float)k / (float)PHN;
        float x, y;
        if (uu < 1.f)      { x = 1.f-uu; y = uu;     }
        else if (uu < 2.f) { x = 1.f-uu; y = 2.f-uu; }
        else if (uu < 3.f) { x = uu-3.f; y = 2.f-uu; }
        else               { x = uu-3.f; y = uu-4.f; }
        float inv = rsqrtf(fmaf(x,x,y*y));
        float px = x*inv, py = y*inv;
        float h = fmaf(px, pp_w1[l*2*HH + j],
                  fmaf(py, pp_w1[l*2*HH + HH + j], pp_b1[l*HH+j]));
        float g = gelu_exact(h);
        float vr = g * pp_w2[(l*HH+j)*2];
        float vi = g * pp_w2[(l*HH+j)*2 + 1];
        #pragma unroll
        for (int o = 16; o; o >>= 1){
            vr += __shfl_down_sync(0xffffffffu, vr, o);
            vi += __shfl_down_sync(0xffffffffu, vi, o);
        }
        if (j == 0) g_phtab[l][k] = make_float2(vr + pp_b2[l*2], vi + pp_b2[l*2+1]);
    }
}

// ---------------------------------------------------------------------------
// Kernel A: embed + complex rotation, write transposed [B][D][S].
// ---------------------------------------------------------------------------
#define TS 16
#define XST 18
__global__ void __launch_bounds__(256) embed_kernel(
    const float* __restrict__ x,
    const float* __restrict__ erw, const float* __restrict__ erb,
    const float* __restrict__ eiw, const float* __restrict__ eib)
{
    __shared__ float xsh[INF*XST];        // [i][s], stride 18
    __shared__ float zshr[DD][TS+1];
    __shared__ float zshi[DD][TS+1];

    int t = threadIdx.x;                  // thread t owns d = t
    int nb_per_b = SS / TS;               // 64
    int b  = blockIdx.x / nb_per_b;
    int s0 = (blockIdx.x % nb_per_b) * TS;

    const float* xp = x + (size_t)(b*SS + s0) * INF;
    for (int e = t; e < TS*INF; e += 256){
        int s = e >> 6, i = e & 63;
        xsh[i*XST + s] = xp[e];
    }
    __syncthreads();

    int d = t;
    float br = erb[d], bi = eib[d];
    u64 ar2[TS/2], ai2[TS/2];
    #pragma unroll
    for (int p = 0; p < TS/2; p++){ ar2[p] = pk2(br, br); ai2[p] = pk2(bi, bi); }

    #pragma unroll 4
    for (int i = 0; i < INF; i++){
        float wr = erw[i*DD + d];
        float wi = eiw[i*DD + d];
        u64 wr2 = pk2(wr, wr), wi2 = pk2(wi, wi);
        const u64* xr = (const u64*)(xsh + i*XST);
        #pragma unroll
        for (int p = 0; p < TS/2; p++){
            u64 xv2 = xr[p];               // broadcast LDS.64
            ar2[p] = fma2(xv2, wr2, ar2[p]);
            ai2[p] = fma2(xv2, wi2, ai2[p]);
        }
    }

    float freq = (float)exp(-9.210340371976184 * (double)d / 256.0);
    float sn, cs, sdl, cdl;
    sincosf((float)s0 * freq, &sn, &cs);
    sincosf(freq, &sdl, &cdl);
    #pragma unroll
    for (int p = 0; p < TS/2; p++){
        float a0, a1, q0, q1;
        upk2(ar2[p], a0, a1);
        upk2(ai2[p], q0, q1);
        zshr[d][2*p]   = a0*cs - q0*sn;
        zshi[d][2*p]   = a0*sn + q0*cs;
        float cn = cs*cdl - sn*sdl;
        float sx = sn*cdl + cs*sdl;
        cs = cn; sn = sx;
        zshr[d][2*p+1] = a1*cs - q1*sn;
        zshi[d][2*p+1] = a1*sn + q1*cs;
        cn = cs*cdl - sn*sdl;
        sx = sn*cdl + cs*sdl;
        cs = cn; sn = sx;
    }
    __syncthreads();

    float* outr = g_zr + (size_t)b * DD * SS;
    float* outi = g_zi + (size_t)b * DD * SS;
    for (int idx = t; idx < DD*TS; idx += 256){
        int dd = idx >> 4;
        int sx = idx & (TS-1);
        outr[dd*SS + s0 + sx] = zshr[dd][sx];
        outi[dd*SS + s0 + sx] = zshi[dd][sx];
    }
}

// ---------------------------------------------------------------------------
// Kernel B: 4 causal polarizing blocks via table lookups.
// ---------------------------------------------------------------------------
#define NT 256
__global__ void __launch_bounds__(NT) layers_kernel()
{
    __shared__ float warp_r[LL][8], warp_i[LL][8];

    int t = threadIdx.x;
    size_t base = (size_t)blockIdx.x * SS;        // blockIdx = b*D + d
    float4 z4r = ((const float4*)(g_zr + base))[t];
    float4 z4i = ((const float4*)(g_zi + base))[t];
    float zr[4] = {z4r.x, z4r.y, z4r.z, z4r.w};
    float zi[4] = {z4i.x, z4i.y, z4i.z, z4i.w};

    float invc[4];
    #pragma unroll
    for (int k = 0; k < 4; k++) invc[k] = 1.0f / (float)(t*4 + k + 1);

    int lane = t & 31, wid = t >> 5;
    const float MAG_INV = (float)(MN-1) / (MAG_HI - MAG_LO);

    #pragma unroll
    for (int l = 0; l < LL; l++){
        // ---- block-wide inclusive scan of zr, zi ----
        float c0r = zr[0], c1r = c0r + zr[1], c2r = c1r + zr[2], c3r = c2r + zr[3];
        float c0i = zi[0], c1i = c0i + zi[1], c2i = c1i + zi[2], c3i = c2i + zi[3];
        float wr_ = c3r, wi_ = c3i;
        #pragma unroll
        for (int o = 1; o < 32; o <<= 1){
            float ur = __shfl_up_sync(0xffffffffu, wr_, o);
            float ui = __shfl_up_sync(0xffffffffu, wi_, o);
            if (lane >= o){ wr_ += ur; wi_ += ui; }
        }
        if (lane == 31){ warp_r[l][wid] = wr_; warp_i[l][wid] = wi_; }
        __syncthreads();                  // per-layer buffer: single barrier
        float offr = 0.f, offi = 0.f;
        #pragma unroll
        for (int w = 0; w < 7; w++){
            if (w < wid){ offr += warp_r[l][w]; offi += warp_i[l][w]; }
        }

        float baser = offr + wr_ - c3r;
        float basei = offi + wi_ - c3i;
        float cumr[4] = {baser + c0r, baser + c1r, baser + c2r, baser + c3r};
        float cumi[4] = {basei + c0i, basei + c1i, basei + c2i, basei + c3i};

        #pragma unroll
        for (int k = 0; k < 4; k++){
            float Ar = cumr[k]*invc[k], Ai = cumi[k]*invc[k];
            float m2 = fmaf(Ar, Ar, Ai*Ai);
            float lm = 0.5f * __logf(m2 + 1e-12f);

            // magnitude table: sd = scale*delta(lm), linear interp, clamped
            float fi = (lm - MAG_LO) * MAG_INV;
            fi = fminf(fmaxf(fi, 0.0f), (float)(MN-1) - 1.001f);
            int   i0 = (int)fi;
            float fr = fi - (float)i0;
            float dv0 = __ldg(&g_magtab[l][i0]);
            float dv1 = __ldg(&g_magtab[l][i0+1]);
            float sd  = fmaf(fr, dv1 - dv0, dv0);

            // diamond angle u in [0,4)
            float ax = fabsf(Ar), ay = fabsf(Ai);
            float q  = ay * rcp_ap(ax + ay + 1e-30f);
            float u  = (Ar >= 0.f) ? q : 2.f - q;
            u        = (Ai >= 0.f) ? u : 4.f - u;
            float pf = u * ((float)PHN * 0.25f);
            float fl = floorf(pf);
            int   p0 = ((int)fl) & (PHN-1);
            int   p1 = (p0 + 1)  & (PHN-1);
            float prf = pf - fl;
            float2 gA = __ldg(&g_phtab[l][p0]);
            float2 gB = __ldg(&g_phtab[l][p1]);
            float gr = fmaf(prf, gB.x - gA.x, gA.x);
            float gi = fmaf(prf, gB.y - gA.y, gA.y);

            float nrm2 = fmaf(gr, gr, gi*gi);
            float invn = rsqrt_ap(fmaxf(nrm2, 1e-24f));
            float r    = __expf(lm + sd) * invn;
            zr[k] = fmaf(r, gr, zr[k]);
            zi[k] = fmaf(r, gi, zi[k]);
        }
    }

    ((float4*)(g_zr + base))[t] = make_float4(zr[0], zr[1], zr[2], zr[3]);
}

// ---------------------------------------------------------------------------
// Kernel C: decode as tiled GEMV. Block = 32 s-values, 256 threads.
// All 32 feature LDGs issued first (MLP=32), then w1 preload overlaps.
// ---------------------------------------------------------------------------
#define DBS 32
__global__ void __launch_bounds__(256) decode_kernel(
    const float* __restrict__ w1, const float* __restrict__ b1,
    const float* __restrict__ w2, const float* __restrict__ b2,
    float* __restrict__ out)
{
    __shared__ float sbuf[DD*HH];   // 32 KB: w1 tile, later partials [8][DBS][HH]
    int t = threadIdx.x;
    int s_loc = t & (DBS-1);
    int grp   = t >> 5;                          // 0..7, 32 d each
    int sg    = blockIdx.x * DBS + s_loc;
    int b = sg >> 10, s = sg & (SS-1);
    const float* fp = g_zr + (size_t)b * DD * SS + (size_t)(grp*32) * SS + s;

    // 1) issue ALL feature loads first — independent addresses, MLP=32
    float f[32];
    #pragma unroll
    for (int dd = 0; dd < 32; dd++) f[dd] = __ldg(fp + (size_t)dd * SS);

    // 2) w1 preload LDGs overlap with the f loads already in flight
    const float4* w1v = (const float4*)w1;
    float4* sv = (float4*)sbuf;
    #pragma unroll
    for (int i = 0; i < DD*HH/4/256; i++) sv[t + i*256] = w1v[t + i*256];
    __syncthreads();

    // 3) pure shared + packed-FMA compute
    u64 acc[16];
    #pragma unroll
    for (int h = 0; h < 16; h++) acc[h] = 0ull;

    #pragma unroll
    for (int dd = 0; dd < 32; dd++){
        u64 f2 = pk2(f[dd], f[dd]);
        const ulonglong2* wrow = (const ulonglong2*)(sbuf + (grp*32 + dd)*HH);
        #pragma unroll
        for (int q = 0; q < 8; q++){
            ulonglong2 wv = wrow[q];             // broadcast LDS.128 = 2 h-pairs
            acc[2*q]   = fma2(f2, wv.x, acc[2*q]);
            acc[2*q+1] = fma2(f2, wv.y, acc[2*q+1]);
        }
    }
    __syncthreads();   // done reading w1 tile; sbuf becomes partials

    ulonglong2* rp = (ulonglong2*)(sbuf + (grp*DBS + s_loc)*HH);
    #pragma unroll
    for (int q = 0; q < 8; q++) rp[q] = make_ulonglong2(acc[2*q], acc[2*q+1]);
    __syncthreads();

    // final: warp wid handles 4 s-values; lane = hidden unit
    int wid = t >> 5, lane = t & 31;
    float bb1 = b1[lane], ww2 = w2[lane], bb2 = b2[0];
    #pragma unroll
    for (int si = wid*4; si < wid*4 + 4; si++){
        float hsum = bb1;
        #pragma unroll
        for (int g = 0; g < 8; g++)
            hsum += sbuf[(g*DBS + si)*HH + lane];
        float y = gelu_exact(hsum) * ww2;
        #pragma unroll
        for (int o = 16; o; o >>= 1) y += __shfl_down_sync(0xffffffffu, y, o);
        if (lane == 0) out[blockIdx.x * DBS + si] = y + bb2;
    }
}

// ---------------------------------------------------------------------------
extern "C" void kernel_launch(void* const* d_in, const int* in_sizes, int n_in,
                              void* d_out, int out_size)
{
    const float* x     = (const float*)d_in[0];
    const float* er_w  = (const float*)d_in[1];
    const float* er_b  = (const float*)d_in[2];
    const float* ei_w  = (const float*)d_in[3];
    const float* ei_b  = (const float*)d_in[4];
    const float* pm_w1 = (const float*)d_in[5];
    const float* pm_b1 = (const float*)d_in[6];
    const float* pm_w2 = (const float*)d_in[7];
    const float* pm_b2 = (const float*)d_in[8];
    const float* pp_w1 = (const float*)d_in[9];
    const float* pp_b1 = (const float*)d_in[10];
    const float* pp_w2 = (const float*)d_in[11];
    const float* pp_b2 = (const float*)d_in[12];
    const float* mscal = (const float*)d_in[13];
    const float* op_w1 = (const float*)d_in[14];
    const float* op_b1 = (const float*)d_in[15];
    const float* op_w2 = (const float*)d_in[16];
    const float* op_b2 = (const float*)d_in[17];
    float* out = (float*)d_out;

    build_tables<<<(LL*(MN+PHN)/8 + 0), 256>>>(
        pm_w1, pm_b1, pm_w2, pm_b2, pp_w1, pp_b1, pp_w2, pp_b2, mscal);
    embed_kernel<<<BB*(SS/TS), 256>>>(x, er_w, er_b, ei_w, ei_b);
    layers_kernel<<<BB*DD, NT>>>();
    decode_kernel<<<BB*SS/DBS, 256>>>(op_w1, op_b1, op_w2, op_b2, out);
}